// round 14
// baseline (speedup 1.0000x reference)
#include <cuda_runtime.h>
#include <math.h>

#define NN 50000
#define NE 800000
#define F  128
#define AP 68   // padded row stride (uints) for bf16x2 smem tiles: conflict-free fragments

// ---- zeroed-by-memset scratch block (degrees only) ----
#define OFF_DEGOUT 0
#define OFF_DEGIN  NN
#define PRE_INTS   (2 * NN)
__device__ int g_pre[PRE_INTS];

__device__ __align__(16) float g_srcnorm[NN];
__device__ __align__(16) float g_dstnorm[NN];
__device__ int   g_offsets[NN + 1];
__device__ int   g_rank[NE];         // edge's arrival rank within its dst (from k_deg)
__device__ int   g_csrsrc[NE];
__device__ int   g_blksums[64];
// bf16-packed feature buffers (2 vals per uint)
__device__ __align__(16) unsigned g_h0[(size_t)NN * F / 2];
__device__ __align__(16) unsigned g_h1[(size_t)NN * F / 2];
__device__ __align__(16) unsigned g_hy[(size_t)NN * 64 / 2];

// ---------------- helpers ----------------
__device__ __forceinline__ unsigned pack_bf2(float lo, float hi) {
    unsigned r;
    asm("cvt.rn.bf16x2.f32 %0, %1, %2;" : "=r"(r) : "f"(hi), "f"(lo));
    return r;
}
#define BF_LO(u) __uint_as_float((u) << 16)
#define BF_HI(u) __uint_as_float((u) & 0xffff0000u)

__device__ __forceinline__ void mma_bf16(
    float& c0, float& c1, float& c2, float& c3,
    unsigned a0, unsigned a1, unsigned a2, unsigned a3,
    unsigned b0, unsigned b1)
{
    asm("mma.sync.aligned.m16n8k16.row.col.f32.bf16.bf16.f32 "
        "{%0,%1,%2,%3},{%4,%5,%6,%7},{%8,%9},{%0,%1,%2,%3};"
        : "+f"(c0), "+f"(c1), "+f"(c2), "+f"(c3)
        : "r"(a0), "r"(a1), "r"(a2), "r"(a3), "r"(b0), "r"(b1));
}

__device__ __forceinline__ int warp_incl_scan(int s, int lane) {
    #pragma unroll
    for (int o = 1; o < 32; o <<= 1) {
        int t = __shfl_up_sync(0xffffffffu, s, o);
        if (lane >= o) s += t;
    }
    return s;
}

#define ACC8(u4) do { \
    a0 += BF_LO((u4).x); a1 += BF_HI((u4).x); \
    a2 += BF_LO((u4).y); a3 += BF_HI((u4).y); \
    a4 += BF_LO((u4).z); a5 += BF_HI((u4).z); \
    a6 += BF_LO((u4).w); a7 += BF_HI((u4).w); } while (0)

// ---------------- preprocessing: rank-recording CSR build, no scatter atomics ----------------
// Pass 1: degrees; the indeg atomic's return value IS the edge's rank within its dst.
__global__ void k_deg(const int* __restrict__ src, const int* __restrict__ dst, int e) {
    int i = blockIdx.x * blockDim.x + threadIdx.x;
    if (i < e) {
        atomicAdd(&g_pre[OFF_DEGOUT + src[i]], 1);
        g_rank[i] = atomicAdd(&g_pre[OFF_DEGIN + dst[i]], 1);
    }
}

// per-1024-block exclusive scan of indeg via warp shuffles
__global__ void k_scan1(int n) {
    __shared__ int warpsum[32];
    int tid = threadIdx.x;
    int i = blockIdx.x * 1024 + tid;
    int lane = tid & 31, wid = tid >> 5;
    int v = (i < n) ? g_pre[OFF_DEGIN + i] : 0;
    int s = warp_incl_scan(v, lane);
    if (lane == 31) warpsum[wid] = s;
    __syncthreads();
    if (wid == 0) warpsum[lane] = warp_incl_scan(warpsum[lane], lane);
    __syncthreads();
    int incl = s + (wid > 0 ? warpsum[wid - 1] : 0);
    if (i < n) g_offsets[i] = incl - v;
    if (tid == 1023) g_blksums[blockIdx.x] = incl;
}

// fused scan2+scan3: block-offset fixup (redundant <=48-element reduce) + offsets/norms
__global__ void __launch_bounds__(256) k_scanfix(int n, int e) {
    __shared__ int s_blkoff;
    int b = blockIdx.x, tid = threadIdx.x;
    int i = b * 256 + tid;
    int grp = (b * 256) >> 10;   // 1024-node scan group (256-blocks never straddle)

    if (tid < 32) {
        int acc = 0;
        for (int bb = tid; bb < grp; bb += 32) acc += g_blksums[bb];
        #pragma unroll
        for (int o = 16; o; o >>= 1) acc += __shfl_xor_sync(0xffffffffu, acc, o);
        if (tid == 0) s_blkoff = acc;
    }
    __syncthreads();

    if (i < n) {
        g_offsets[i] += s_blkoff;
        int od = g_pre[OFF_DEGOUT + i];
        int id = g_pre[OFF_DEGIN + i];
        g_srcnorm[i] = od > 0 ? rsqrtf((float)od) : 0.f;
        g_dstnorm[i] = id > 0 ? rsqrtf((float)id) : 0.f;
    }
    if (b == 0 && tid == 0) g_offsets[n] = e;
}

// fused: atomic-free CSR scatter (blocks [0, eb)) + h0 = bf16(features * src_norm)
__global__ void k_scatter_scale(
    const int* __restrict__ src, const int* __restrict__ dst,
    const float* __restrict__ feats, int e, int n, int eb)
{
    int b = blockIdx.x;
    if (b < eb) {
        int i = b * 256 + threadIdx.x;
        if (i < e) {
            int d = dst[i];
            g_csrsrc[g_offsets[d] + g_rank[i]] = src[i];
        }
    } else {
        int i = (b - eb) * 256 + threadIdx.x;   // over n * (F/4)
        if (i < n * (F / 4)) {
            int row = i >> 5;
            float4 v = ((const float4*)feats)[i];
            float s = g_srcnorm[row];
            uint2 o;
            o.x = pack_bf2(v.x * s, v.y * s);
            o.y = pack_bf2(v.z * s, v.w * s);
            ((uint2*)g_h0)[i] = o;
        }
    }
}

// ---------------- fused conv layer: half-warp uint4 gather + bf16 MMA + relu + fold ----
// 5 blocks/SM (40 warps); u[4] staging keeps regs under the 48 budget.
__global__ void __launch_bounds__(256, 5) k_layer128(
    const unsigned* __restrict__ xs,      // bf16-packed, row = 16 uint4
    const float* __restrict__ W,          // [F][F] row-major fp32
    const float* __restrict__ bias,
    unsigned* __restrict__ out,           // bf16-packed output
    int n, int numTiles)
{
    __shared__ unsigned shWb[F * AP];
    __shared__ __align__(16) unsigned shAb[16 * AP];
    __shared__ float    shB[F];

    int tid = threadIdx.x;
    for (int i = tid; i < F * (F / 2); i += 256) {
        int k2 = i >> 7, nn = i & (F - 1);
        shWb[nn * AP + k2] = pack_bf2(W[(2 * k2) * F + nn], W[(2 * k2 + 1) * F + nn]);
    }
    if (tid < F / 4) ((float4*)shB)[tid] = ((const float4*)bias)[tid];
    __syncthreads();

    int w = tid >> 5, lane = tid & 31;
    int g = lane >> 2, tig = lane & 3;
    int half = lane >> 4, hl = lane & 15;
    const uint4* xr = (const uint4*)xs;

    for (int t = blockIdx.x; t < numTiles; t += gridDim.x) {
        int base = t * 16;

        #pragma unroll
        for (int s2 = 0; s2 < 2; s2++) {
            int ml = w + s2 * 8;
            int m = base + ml;
            float a0 = 0.f, a1 = 0.f, a2 = 0.f, a3 = 0.f;
            float a4 = 0.f, a5 = 0.f, a6 = 0.f, a7 = 0.f;
            int e = 0, end = 0;
            if (m < n) { e = g_offsets[m]; end = g_offsets[m + 1]; }
            for (; e + 8 <= end; e += 8) {
                uint4 u[4];
                #pragma unroll
                for (int q = 0; q < 4; q++) {
                    int idx = g_csrsrc[e + 2 * q + half];
                    u[q] = xr[(size_t)idx * 16 + hl];
                }
                #pragma unroll
                for (int q = 0; q < 4; q++) ACC8(u[q]);
            }
            for (; e + 2 <= end; e += 2) {
                int idx = g_csrsrc[e + half];
                uint4 u = xr[(size_t)idx * 16 + hl];
                ACC8(u);
            }
            if (e < end && half == 0) {
                int idx = g_csrsrc[e];
                uint4 u = xr[(size_t)idx * 16 + hl];
                ACC8(u);
            }
            // combine the two halves
            a0 += __shfl_xor_sync(0xffffffffu, a0, 16);
            a1 += __shfl_xor_sync(0xffffffffu, a1, 16);
            a2 += __shfl_xor_sync(0xffffffffu, a2, 16);
            a3 += __shfl_xor_sync(0xffffffffu, a3, 16);
            a4 += __shfl_xor_sync(0xffffffffu, a4, 16);
            a5 += __shfl_xor_sync(0xffffffffu, a5, 16);
            a6 += __shfl_xor_sync(0xffffffffu, a6, 16);
            a7 += __shfl_xor_sync(0xffffffffu, a7, 16);
            float dn = (m < n) ? g_dstnorm[m] : 0.f;
            if (half == 0) {
                unsigned* p = shAb + ml * AP + hl * 4;
                p[0] = pack_bf2(a0 * dn, a1 * dn);
                p[1] = pack_bf2(a2 * dn, a3 * dn);
                p[2] = pack_bf2(a4 * dn, a5 * dn);
                p[3] = pack_bf2(a6 * dn, a7 * dn);
            }
        }
        __syncthreads();

        // --- GEMM: warp w owns cols [16w, 16w+16) ---
        int nb0 = w * 16, nb1 = nb0 + 8;
        float2 bb0 = *(float2*)(shB + nb0 + 2 * tig);
        float2 bb1 = *(float2*)(shB + nb1 + 2 * tig);
        float c00 = bb0.x, c01 = bb0.y, c02 = bb0.x, c03 = bb0.y;
        float c10 = bb1.x, c11 = bb1.y, c12 = bb1.x, c13 = bb1.y;

        const unsigned* A0 = shAb + g * AP;
        const unsigned* A1 = shAb + (g + 8) * AP;
        const unsigned* B0 = shWb + (nb0 + g) * AP;
        const unsigned* B1 = shWb + (nb1 + g) * AP;
        #pragma unroll
        for (int kt = 0; kt < 8; kt++) {
            int j0 = kt * 8;
            unsigned f0 = A0[j0 + tig],     f1 = A1[j0 + tig];
            unsigned f2 = A0[j0 + 4 + tig], f3 = A1[j0 + 4 + tig];
            mma_bf16(c00, c01, c02, c03, f0, f1, f2, f3, B0[j0 + tig], B0[j0 + 4 + tig]);
            mma_bf16(c10, c11, c12, c13, f0, f1, f2, f3, B1[j0 + tig], B1[j0 + 4 + tig]);
        }

        int m0 = base + g, m1 = base + g + 8;
        if (m0 < n) {
            float sn = g_srcnorm[m0];
            unsigned* o = out + (size_t)m0 * (F / 2);
            o[nb0 / 2 + tig] = pack_bf2(fmaxf(c00, 0.f) * sn, fmaxf(c01, 0.f) * sn);
            o[nb1 / 2 + tig] = pack_bf2(fmaxf(c10, 0.f) * sn, fmaxf(c11, 0.f) * sn);
        }
        if (m1 < n) {
            float sn = g_srcnorm[m1];
            unsigned* o = out + (size_t)m1 * (F / 2);
            o[nb0 / 2 + tig] = pack_bf2(fmaxf(c02, 0.f) * sn, fmaxf(c03, 0.f) * sn);
            o[nb1 / 2 + tig] = pack_bf2(fmaxf(c12, 0.f) * sn, fmaxf(c13, 0.f) * sn);
        }
        __syncthreads();
    }
}

// ---------------- y = x2s @ W3 via bf16 MMA (static tiles) ----------------
__global__ void __launch_bounds__(256) k_pre3(
    const unsigned* __restrict__ x,       // bf16-packed, row stride 64 uints
    const float* __restrict__ W3,         // [F][64] row-major fp32
    unsigned* __restrict__ y, int n, int numTiles)
{
    __shared__ unsigned shWb[64 * AP];
    __shared__ unsigned shXb[16 * AP];
    int tid = threadIdx.x;
    for (int i = tid; i < 64 * (F / 2); i += 256) {
        int k2 = i >> 6, nn = i & 63;
        shWb[nn * AP + k2] = pack_bf2(W3[(2 * k2) * 64 + nn], W3[(2 * k2 + 1) * 64 + nn]);
    }
    __syncthreads();

    int w = tid >> 5, lane = tid & 31;
    int g = lane >> 2, tig = lane & 3;

    for (int t = blockIdx.x; t < numTiles; t += gridDim.x) {
        int base = t * 16;
        {
            int r = tid >> 4, q = tid & 15;
            int node = base + r;
            uint4 v = (node < n) ? ((const uint4*)(x + (size_t)node * 64))[q]
                                 : make_uint4(0u, 0u, 0u, 0u);
            unsigned* p = shXb + r * AP + q * 4;
            p[0] = v.x; p[1] = v.y; p[2] = v.z; p[3] = v.w;
        }
        __syncthreads();

        int nb = w * 8;
        float c0 = 0.f, c1 = 0.f, c2 = 0.f, c3 = 0.f;
        const unsigned* A0 = shXb + g * AP;
        const unsigned* A1 = shXb + (g + 8) * AP;
        const unsigned* B0 = shWb + (nb + g) * AP;
        #pragma unroll
        for (int kt = 0; kt < 8; kt++) {
            int j0 = kt * 8;
            mma_bf16(c0, c1, c2, c3,
                     A0[j0 + tig], A1[j0 + tig], A0[j0 + 4 + tig], A1[j0 + 4 + tig],
                     B0[j0 + tig], B0[j0 + 4 + tig]);
        }
        int m0 = base + g, m1 = base + g + 8;
        if (m0 < n) y[(size_t)m0 * 32 + nb / 2 + tig] = pack_bf2(c0, c1);
        if (m1 < n) y[(size_t)m1 * 32 + nb / 2 + tig] = pack_bf2(c2, c3);
        __syncthreads();
    }
}

// ---------------- layer 3: quarter-warp uint4 gather + bias/relu/head/sigmoid ----------------
__global__ void __launch_bounds__(256) k_layer3(
    const unsigned* __restrict__ y, const float* __restrict__ b3,
    const float* __restrict__ Wp, const float* __restrict__ bp,
    float* __restrict__ out, int n)
{
    int gw = (blockIdx.x * blockDim.x + threadIdx.x) >> 5;   // warp per node
    int lane = threadIdx.x & 31;
    if (gw >= n) return;
    int sub = lane >> 3, ql = lane & 7;   // 4 edge slots x 8 lanes (uint4 each = 8 cols)
    int e = g_offsets[gw], end = g_offsets[gw + 1];
    const uint4* yr = (const uint4*)y;    // row = 8 uint4
    float a0 = 0.f, a1 = 0.f, a2 = 0.f, a3 = 0.f;
    float a4 = 0.f, a5 = 0.f, a6 = 0.f, a7 = 0.f;

    for (; e + 32 <= end; e += 32) {
        uint4 u[8];
        #pragma unroll
        for (int q = 0; q < 8; q++) {
            int idx = g_csrsrc[e + 4 * q + sub];
            u[q] = yr[(size_t)idx * 8 + ql];
        }
        #pragma unroll
        for (int q = 0; q < 8; q++) ACC8(u[q]);
    }
    for (; e + 4 <= end; e += 4) {
        int idx = g_csrsrc[e + sub];
        uint4 u = yr[(size_t)idx * 8 + ql];
        ACC8(u);
    }
    int r = end - e;
    if (sub < r) {
        int idx = g_csrsrc[e + sub];
        uint4 u = yr[(size_t)idx * 8 + ql];
        ACC8(u);
    }
    // reduce over the 4 edge slots (xor 8, 16)
    #pragma unroll
    for (int o = 8; o <= 16; o <<= 1) {
        a0 += __shfl_xor_sync(0xffffffffu, a0, o);
        a1 += __shfl_xor_sync(0xffffffffu, a1, o);
        a2 += __shfl_xor_sync(0xffffffffu, a2, o);
        a3 += __shfl_xor_sync(0xffffffffu, a3, o);
        a4 += __shfl_xor_sync(0xffffffffu, a4, o);
        a5 += __shfl_xor_sync(0xffffffffu, a5, o);
        a6 += __shfl_xor_sync(0xffffffffu, a6, o);
        a7 += __shfl_xor_sync(0xffffffffu, a7, o);
    }
    float dn = g_dstnorm[gw];
    float4 ba = *(const float4*)(b3 + ql * 8);
    float4 bb = *(const float4*)(b3 + ql * 8 + 4);
    float4 wa = *(const float4*)(Wp + ql * 8);
    float4 wb = *(const float4*)(Wp + ql * 8 + 4);
    float p = fmaxf(a0 * dn + ba.x, 0.f) * wa.x + fmaxf(a1 * dn + ba.y, 0.f) * wa.y
            + fmaxf(a2 * dn + ba.z, 0.f) * wa.z + fmaxf(a3 * dn + ba.w, 0.f) * wa.w
            + fmaxf(a4 * dn + bb.x, 0.f) * wb.x + fmaxf(a5 * dn + bb.y, 0.f) * wb.y
            + fmaxf(a6 * dn + bb.z, 0.f) * wb.z + fmaxf(a7 * dn + bb.w, 0.f) * wb.w;
    p += __shfl_xor_sync(0xffffffffu, p, 1);
    p += __shfl_xor_sync(0xffffffffu, p, 2);
    p += __shfl_xor_sync(0xffffffffu, p, 4);
    if (lane == 0) {
        float l = p + bp[0];
        out[gw] = 1.f / (1.f + __expf(-l));
    }
}

// ---------------- launch ----------------
extern "C" void kernel_launch(void* const* d_in, const int* in_sizes, int n_in,
                              void* d_out, int out_size)
{
    const float* feats = (const float*)d_in[0];
    const int*   src   = (const int*)d_in[1];
    const int*   dst   = (const int*)d_in[2];
    // d_in[3] = edge_types (unused)
    const float* W1 = (const float*)d_in[4];
    const float* b1 = (const float*)d_in[5];
    const float* W2 = (const float*)d_in[6];
    const float* b2 = (const float*)d_in[7];
    const float* W3 = (const float*)d_in[8];
    const float* b3 = (const float*)d_in[9];
    const float* Wp = (const float*)d_in[10];
    const float* bp = (const float*)d_in[11];
    float* out = (float*)d_out;

    int n = in_sizes[0] / F;   // 50000
    int e = in_sizes[1];       // 800000

    unsigned *h0, *h1, *hy;
    int* prep;
    cudaGetSymbolAddress((void**)&h0, g_h0);
    cudaGetSymbolAddress((void**)&h1, g_h1);
    cudaGetSymbolAddress((void**)&hy, g_hy);
    cudaGetSymbolAddress((void**)&prep, g_pre);

    int nb = (n + 1023) / 1024;
    int tiles = (n + 15) / 16;
    int eb = (e + 255) / 256;
    int sb = (n * (F / 4) + 255) / 256;

    cudaMemsetAsync(prep, 0, sizeof(int) * PRE_INTS);
    k_deg          <<<(e + 255) / 256, 256>>>(src, dst, e);
    k_scan1        <<<nb, 1024>>>(n);
    k_scanfix      <<<(n + 255) / 256, 256>>>(n, e);
    k_scatter_scale<<<eb + sb, 256>>>(src, dst, feats, e, n, eb);

    k_layer128<<<740, 256>>>(h0, W1, b1, h1, n, tiles);
    k_layer128<<<740, 256>>>(h1, W2, b2, h0, n, tiles);
    k_pre3    <<<1184, 256>>>(h0, W3, hy, n, tiles);
    k_layer3  <<<(n * 32 + 255) / 256, 256>>>(hy, b3, Wp, bp, out, n);
}

// round 15
// speedup vs baseline: 1.0593x; 1.0593x over previous
#include <cuda_runtime.h>
#include <math.h>

#define NN 50000
#define NE 800000
#define F  128
#define AP 68   // padded row stride (uints) for bf16x2 smem tiles: conflict-free fragments

// ---- zeroed-by-memset scratch block (degrees only) ----
#define OFF_DEGOUT 0
#define OFF_DEGIN  NN
#define PRE_INTS   (2 * NN)
__device__ int g_pre[PRE_INTS];

__device__ __align__(16) float g_srcnorm[NN];
__device__ __align__(16) float g_dstnorm[NN];
__device__ int   g_offsets[NN + 1];
__device__ int   g_cursor[NN];
__device__ int   g_csrsrc[NE];
__device__ int   g_blksums[64];
// bf16-packed feature buffers (2 vals per uint)
__device__ __align__(16) unsigned g_h0[(size_t)NN * F / 2];
__device__ __align__(16) unsigned g_h1[(size_t)NN * F / 2];
__device__ __align__(16) unsigned g_hy[(size_t)NN * 64 / 2];
// pre-converted weights: bf16x2, [n][k/2] transposed layout (64 uints per row)
__device__ __align__(16) unsigned g_w1b[F * 64];
__device__ __align__(16) unsigned g_w2b[F * 64];
__device__ __align__(16) unsigned g_w3b[64 * 64];

// ---------------- helpers ----------------
__device__ __forceinline__ unsigned pack_bf2(float lo, float hi) {
    unsigned r;
    asm("cvt.rn.bf16x2.f32 %0, %1, %2;" : "=r"(r) : "f"(hi), "f"(lo));
    return r;
}
#define BF_LO(u) __uint_as_float((u) << 16)
#define BF_HI(u) __uint_as_float((u) & 0xffff0000u)

__device__ __forceinline__ void mma_bf16(
    float& c0, float& c1, float& c2, float& c3,
    unsigned a0, unsigned a1, unsigned a2, unsigned a3,
    unsigned b0, unsigned b1)
{
    asm("mma.sync.aligned.m16n8k16.row.col.f32.bf16.bf16.f32 "
        "{%0,%1,%2,%3},{%4,%5,%6,%7},{%8,%9},{%0,%1,%2,%3};"
        : "+f"(c0), "+f"(c1), "+f"(c2), "+f"(c3)
        : "r"(a0), "r"(a1), "r"(a2), "r"(a3), "r"(b0), "r"(b1));
}

__device__ __forceinline__ int warp_incl_scan(int s, int lane) {
    #pragma unroll
    for (int o = 1; o < 32; o <<= 1) {
        int t = __shfl_up_sync(0xffffffffu, s, o);
        if (lane >= o) s += t;
    }
    return s;
}

#define ACC8(u4) do { \
    a0 += BF_LO((u4).x); a1 += BF_HI((u4).x); \
    a2 += BF_LO((u4).y); a3 += BF_HI((u4).y); \
    a4 += BF_LO((u4).z); a5 += BF_HI((u4).z); \
    a6 += BF_LO((u4).w); a7 += BF_HI((u4).w); } while (0)

// ---------------- preprocessing ----------------
// Heterogeneous grid: degree blocks [0, eb) + W-conversion blocks [eb, eb+80).
// W conversion (independent work) rides free behind the degree atomics.
__global__ void k_deg_conv(
    const int* __restrict__ src, const int* __restrict__ dst,
    const float* __restrict__ W1, const float* __restrict__ W2,
    const float* __restrict__ W3, int e, int eb)
{
    int b = blockIdx.x;
    if (b < eb) {
        int i = b * 256 + threadIdx.x;
        if (i < e) {
            atomicAdd(&g_pre[OFF_DEGOUT + src[i]], 1);
            atomicAdd(&g_pre[OFF_DEGIN + dst[i]], 1);
        }
    } else {
        int j = (b - eb) * 256 + threadIdx.x;
        if (j < 8192) {                       // W1: [128][128] -> [nn][k2]
            int nn = j & (F - 1), k2 = j >> 7;
            g_w1b[nn * 64 + k2] = pack_bf2(W1[(2 * k2) * F + nn], W1[(2 * k2 + 1) * F + nn]);
        } else if (j < 16384) {               // W2
            int j2 = j - 8192;
            int nn = j2 & (F - 1), k2 = j2 >> 7;
            g_w2b[nn * 64 + k2] = pack_bf2(W2[(2 * k2) * F + nn], W2[(2 * k2 + 1) * F + nn]);
        } else if (j < 20480) {               // W3: [128][64] -> [nn<64][k2<64]
            int j2 = j - 16384;
            int nn = j2 & 63, k2 = j2 >> 6;
            g_w3b[nn * 64 + k2] = pack_bf2(W3[(2 * k2) * 64 + nn], W3[(2 * k2 + 1) * 64 + nn]);
        }
    }
}

// per-1024-block exclusive scan of indeg via warp shuffles
__global__ void k_scan1(int n) {
    __shared__ int warpsum[32];
    int tid = threadIdx.x;
    int i = blockIdx.x * 1024 + tid;
    int lane = tid & 31, wid = tid >> 5;
    int v = (i < n) ? g_pre[OFF_DEGIN + i] : 0;
    int s = warp_incl_scan(v, lane);
    if (lane == 31) warpsum[wid] = s;
    __syncthreads();
    if (wid == 0) warpsum[lane] = warp_incl_scan(warpsum[lane], lane);
    __syncthreads();
    int incl = s + (wid > 0 ? warpsum[wid - 1] : 0);
    if (i < n) g_offsets[i] = incl - v;
    if (tid == 1023) g_blksums[blockIdx.x] = incl;
}

// fused scan2+scan3: block-offset fixup (redundant <=48-element reduce) + offsets/cursor/norms
__global__ void __launch_bounds__(256) k_scanfix(int n, int e) {
    __shared__ int s_blkoff;
    int b = blockIdx.x, tid = threadIdx.x;
    int i = b * 256 + tid;
    int grp = (b * 256) >> 10;   // 1024-node scan group (256-blocks never straddle)

    if (tid < 32) {
        int acc = 0;
        for (int bb = tid; bb < grp; bb += 32) acc += g_blksums[bb];
        #pragma unroll
        for (int o = 16; o; o >>= 1) acc += __shfl_xor_sync(0xffffffffu, acc, o);
        if (tid == 0) s_blkoff = acc;
    }
    __syncthreads();

    if (i < n) {
        int o = g_offsets[i] + s_blkoff;
        g_offsets[i] = o;
        g_cursor[i] = o;
        int od = g_pre[OFF_DEGOUT + i];
        int id = g_pre[OFF_DEGIN + i];
        g_srcnorm[i] = od > 0 ? rsqrtf((float)od) : 0.f;
        g_dstnorm[i] = id > 0 ? rsqrtf((float)id) : 0.f;
    }
    if (b == 0 && tid == 0) g_offsets[n] = e;
}

// fused: CSR scatter (blocks [0, eb)) + h0 = bf16(features * src_norm) (blocks [eb, ...))
__global__ void k_scatter_scale(
    const int* __restrict__ src, const int* __restrict__ dst,
    const float* __restrict__ feats, int e, int n, int eb)
{
    int b = blockIdx.x;
    if (b < eb) {
        int i = b * 256 + threadIdx.x;
        if (i < e) {
            int d = dst[i];
            int pos = atomicAdd(&g_cursor[d], 1);
            g_csrsrc[pos] = src[i];
        }
    } else {
        int i = (b - eb) * 256 + threadIdx.x;   // over n * (F/4)
        if (i < n * (F / 4)) {
            int row = i >> 5;
            float4 v = ((const float4*)feats)[i];
            float s = g_srcnorm[row];
            uint2 o;
            o.x = pack_bf2(v.x * s, v.y * s);
            o.y = pack_bf2(v.z * s, v.w * s);
            ((uint2*)g_h0)[i] = o;
        }
    }
}

// ---------------- fused conv layer: half-warp uint4 gather + bf16 MMA + relu + fold ----
// 5 blocks/SM (40 warps); W preamble is a pure uint4 copy from pre-converted gmem.
__global__ void __launch_bounds__(256, 5) k_layer128(
    const unsigned* __restrict__ xs,      // bf16-packed, row = 16 uint4
    const unsigned* __restrict__ wb,      // pre-converted bf16x2 W, [nn][64 uints]
    const float* __restrict__ bias,
    unsigned* __restrict__ out,           // bf16-packed output
    int n, int numTiles)
{
    __shared__ unsigned shWb[F * AP];
    __shared__ __align__(16) unsigned shAb[16 * AP];
    __shared__ float    shB[F];

    int tid = threadIdx.x;
    const uint4* w4 = (const uint4*)wb;
    for (int i = tid; i < F * 16; i += 256) {
        int nn = i >> 4, q = i & 15;
        *(uint4*)(shWb + nn * AP + q * 4) = w4[i];
    }
    if (tid < F / 4) ((float4*)shB)[tid] = ((const float4*)bias)[tid];
    __syncthreads();

    int w = tid >> 5, lane = tid & 31;
    int g = lane >> 2, tig = lane & 3;
    int half = lane >> 4, hl = lane & 15;
    const uint4* xr = (const uint4*)xs;

    for (int t = blockIdx.x; t < numTiles; t += gridDim.x) {
        int base = t * 16;

        #pragma unroll
        for (int s2 = 0; s2 < 2; s2++) {
            int ml = w + s2 * 8;
            int m = base + ml;
            float a0 = 0.f, a1 = 0.f, a2 = 0.f, a3 = 0.f;
            float a4 = 0.f, a5 = 0.f, a6 = 0.f, a7 = 0.f;
            int e = 0, end = 0;
            if (m < n) { e = g_offsets[m]; end = g_offsets[m + 1]; }
            for (; e + 8 <= end; e += 8) {
                uint4 u[4];
                #pragma unroll
                for (int q = 0; q < 4; q++) {
                    int idx = g_csrsrc[e + 2 * q + half];
                    u[q] = xr[(size_t)idx * 16 + hl];
                }
                #pragma unroll
                for (int q = 0; q < 4; q++) ACC8(u[q]);
            }
            for (; e + 2 <= end; e += 2) {
                int idx = g_csrsrc[e + half];
                uint4 u = xr[(size_t)idx * 16 + hl];
                ACC8(u);
            }
            if (e < end && half == 0) {
                int idx = g_csrsrc[e];
                uint4 u = xr[(size_t)idx * 16 + hl];
                ACC8(u);
            }
            // combine the two halves
            a0 += __shfl_xor_sync(0xffffffffu, a0, 16);
            a1 += __shfl_xor_sync(0xffffffffu, a1, 16);
            a2 += __shfl_xor_sync(0xffffffffu, a2, 16);
            a3 += __shfl_xor_sync(0xffffffffu, a3, 16);
            a4 += __shfl_xor_sync(0xffffffffu, a4, 16);
            a5 += __shfl_xor_sync(0xffffffffu, a5, 16);
            a6 += __shfl_xor_sync(0xffffffffu, a6, 16);
            a7 += __shfl_xor_sync(0xffffffffu, a7, 16);
            float dn = (m < n) ? g_dstnorm[m] : 0.f;
            if (half == 0) {
                unsigned* p = shAb + ml * AP + hl * 4;
                p[0] = pack_bf2(a0 * dn, a1 * dn);
                p[1] = pack_bf2(a2 * dn, a3 * dn);
                p[2] = pack_bf2(a4 * dn, a5 * dn);
                p[3] = pack_bf2(a6 * dn, a7 * dn);
            }
        }
        __syncthreads();

        // --- GEMM: warp w owns cols [16w, 16w+16) ---
        int nb0 = w * 16, nb1 = nb0 + 8;
        float2 bb0 = *(float2*)(shB + nb0 + 2 * tig);
        float2 bb1 = *(float2*)(shB + nb1 + 2 * tig);
        float c00 = bb0.x, c01 = bb0.y, c02 = bb0.x, c03 = bb0.y;
        float c10 = bb1.x, c11 = bb1.y, c12 = bb1.x, c13 = bb1.y;

        const unsigned* A0 = shAb + g * AP;
        const unsigned* A1 = shAb + (g + 8) * AP;
        const unsigned* B0 = shWb + (nb0 + g) * AP;
        const unsigned* B1 = shWb + (nb1 + g) * AP;
        #pragma unroll
        for (int kt = 0; kt < 8; kt++) {
            int j0 = kt * 8;
            unsigned f0 = A0[j0 + tig],     f1 = A1[j0 + tig];
            unsigned f2 = A0[j0 + 4 + tig], f3 = A1[j0 + 4 + tig];
            mma_bf16(c00, c01, c02, c03, f0, f1, f2, f3, B0[j0 + tig], B0[j0 + 4 + tig]);
            mma_bf16(c10, c11, c12, c13, f0, f1, f2, f3, B1[j0 + tig], B1[j0 + 4 + tig]);
        }

        int m0 = base + g, m1 = base + g + 8;
        if (m0 < n) {
            float sn = g_srcnorm[m0];
            unsigned* o = out + (size_t)m0 * (F / 2);
            o[nb0 / 2 + tig] = pack_bf2(fmaxf(c00, 0.f) * sn, fmaxf(c01, 0.f) * sn);
            o[nb1 / 2 + tig] = pack_bf2(fmaxf(c10, 0.f) * sn, fmaxf(c11, 0.f) * sn);
        }
        if (m1 < n) {
            float sn = g_srcnorm[m1];
            unsigned* o = out + (size_t)m1 * (F / 2);
            o[nb0 / 2 + tig] = pack_bf2(fmaxf(c02, 0.f) * sn, fmaxf(c03, 0.f) * sn);
            o[nb1 / 2 + tig] = pack_bf2(fmaxf(c12, 0.f) * sn, fmaxf(c13, 0.f) * sn);
        }
        __syncthreads();
    }
}

// ---------------- y = x2s @ W3 via bf16 MMA (pre-converted W3, uint4 preamble) ----------------
__global__ void __launch_bounds__(256) k_pre3(
    const unsigned* __restrict__ x,       // bf16-packed, row stride 64 uints
    unsigned* __restrict__ y, int n, int numTiles)
{
    __shared__ unsigned shWb[64 * AP];
    __shared__ unsigned shXb[16 * AP];
    int tid = threadIdx.x;
    const uint4* w4 = (const uint4*)g_w3b;
    for (int i = tid; i < 64 * 16; i += 256) {
        int nn = i >> 4, q = i & 15;
        *(uint4*)(shWb + nn * AP + q * 4) = w4[i];
    }
    __syncthreads();

    int w = tid >> 5, lane = tid & 31;
    int g = lane >> 2, tig = lane & 3;

    for (int t = blockIdx.x; t < numTiles; t += gridDim.x) {
        int base = t * 16;
        {
            int r = tid >> 4, q = tid & 15;
            int node = base + r;
            uint4 v = (node < n) ? ((const uint4*)(x + (size_t)node * 64))[q]
                                 : make_uint4(0u, 0u, 0u, 0u);
            unsigned* p = shXb + r * AP + q * 4;
            p[0] = v.x; p[1] = v.y; p[2] = v.z; p[3] = v.w;
        }
        __syncthreads();

        int nb = w * 8;
        float c0 = 0.f, c1 = 0.f, c2 = 0.f, c3 = 0.f;
        const unsigned* A0 = shXb + g * AP;
        const unsigned* A1 = shXb + (g + 8) * AP;
        const unsigned* B0 = shWb + (nb + g) * AP;
        #pragma unroll
        for (int kt = 0; kt < 8; kt++) {
            int j0 = kt * 8;
            mma_bf16(c0, c1, c2, c3,
                     A0[j0 + tig], A1[j0 + tig], A0[j0 + 4 + tig], A1[j0 + 4 + tig],
                     B0[j0 + tig], B0[j0 + 4 + tig]);
        }
        int m0 = base + g, m1 = base + g + 8;
        if (m0 < n) y[(size_t)m0 * 32 + nb / 2 + tig] = pack_bf2(c0, c1);
        if (m1 < n) y[(size_t)m1 * 32 + nb / 2 + tig] = pack_bf2(c2, c3);
        __syncthreads();
    }
}

// ---------------- layer 3: quarter-warp uint4 gather + bias/relu/head/sigmoid ----------------
__global__ void __launch_bounds__(256) k_layer3(
    const unsigned* __restrict__ y, const float* __restrict__ b3,
    const float* __restrict__ Wp, const float* __restrict__ bp,
    float* __restrict__ out, int n)
{
    int gw = (blockIdx.x * blockDim.x + threadIdx.x) >> 5;   // warp per node
    int lane = threadIdx.x & 31;
    if (gw >= n) return;
    int sub = lane >> 3, ql = lane & 7;   // 4 edge slots x 8 lanes (uint4 each = 8 cols)
    int e = g_offsets[gw], end = g_offsets[gw + 1];
    const uint4* yr = (const uint4*)y;    // row = 8 uint4
    float a0 = 0.f, a1 = 0.f, a2 = 0.f, a3 = 0.f;
    float a4 = 0.f, a5 = 0.f, a6 = 0.f, a7 = 0.f;

    for (; e + 32 <= end; e += 32) {
        uint4 u[8];
        #pragma unroll
        for (int q = 0; q < 8; q++) {
            int idx = g_csrsrc[e + 4 * q + sub];
            u[q] = yr[(size_t)idx * 8 + ql];
        }
        #pragma unroll
        for (int q = 0; q < 8; q++) ACC8(u[q]);
    }
    for (; e + 4 <= end; e += 4) {
        int idx = g_csrsrc[e + sub];
        uint4 u = yr[(size_t)idx * 8 + ql];
        ACC8(u);
    }
    int r = end - e;
    if (sub < r) {
        int idx = g_csrsrc[e + sub];
        uint4 u = yr[(size_t)idx * 8 + ql];
        ACC8(u);
    }
    // reduce over the 4 edge slots (xor 8, 16)
    #pragma unroll
    for (int o = 8; o <= 16; o <<= 1) {
        a0 += __shfl_xor_sync(0xffffffffu, a0, o);
        a1 += __shfl_xor_sync(0xffffffffu, a1, o);
        a2 += __shfl_xor_sync(0xffffffffu, a2, o);
        a3 += __shfl_xor_sync(0xffffffffu, a3, o);
        a4 += __shfl_xor_sync(0xffffffffu, a4, o);
        a5 += __shfl_xor_sync(0xffffffffu, a5, o);
        a6 += __shfl_xor_sync(0xffffffffu, a6, o);
        a7 += __shfl_xor_sync(0xffffffffu, a7, o);
    }
    float dn = g_dstnorm[gw];
    float4 ba = *(const float4*)(b3 + ql * 8);
    float4 bb = *(const float4*)(b3 + ql * 8 + 4);
    float4 wa = *(const float4*)(Wp + ql * 8);
    float4 wb = *(const float4*)(Wp + ql * 8 + 4);
    float p = fmaxf(a0 * dn + ba.x, 0.f) * wa.x + fmaxf(a1 * dn + ba.y, 0.f) * wa.y
            + fmaxf(a2 * dn + ba.z, 0.f) * wa.z + fmaxf(a3 * dn + ba.w, 0.f) * wa.w
            + fmaxf(a4 * dn + bb.x, 0.f) * wb.x + fmaxf(a5 * dn + bb.y, 0.f) * wb.y
            + fmaxf(a6 * dn + bb.z, 0.f) * wb.z + fmaxf(a7 * dn + bb.w, 0.f) * wb.w;
    p += __shfl_xor_sync(0xffffffffu, p, 1);
    p += __shfl_xor_sync(0xffffffffu, p, 2);
    p += __shfl_xor_sync(0xffffffffu, p, 4);
    if (lane == 0) {
        float l = p + bp[0];
        out[gw] = 1.f / (1.f + __expf(-l));
    }
}

// ---------------- launch ----------------
extern "C" void kernel_launch(void* const* d_in, const int* in_sizes, int n_in,
                              void* d_out, int out_size)
{
    const float* feats = (const float*)d_in[0];
    const int*   src   = (const int*)d_in[1];
    const int*   dst   = (const int*)d_in[2];
    // d_in[3] = edge_types (unused)
    const float* W1 = (const float*)d_in[4];
    const float* b1 = (const float*)d_in[5];
    const float* W2 = (const float*)d_in[6];
    const float* b2 = (const float*)d_in[7];
    const float* W3 = (const float*)d_in[8];
    const float* b3 = (const float*)d_in[9];
    const float* Wp = (const float*)d_in[10];
    const float* bp = (const float*)d_in[11];
    float* out = (float*)d_out;

    int n = in_sizes[0] / F;   // 50000
    int e = in_sizes[1];       // 800000

    unsigned *h0, *h1, *hy, *w1b, *w2b;
    int* prep;
    cudaGetSymbolAddress((void**)&h0, g_h0);
    cudaGetSymbolAddress((void**)&h1, g_h1);
    cudaGetSymbolAddress((void**)&hy, g_hy);
    cudaGetSymbolAddress((void**)&w1b, g_w1b);
    cudaGetSymbolAddress((void**)&w2b, g_w2b);
    cudaGetSymbolAddress((void**)&prep, g_pre);

    int nb = (n + 1023) / 1024;
    int tiles = (n + 15) / 16;
    int eb = (e + 255) / 256;                // 3125
    int sb = (n * (F / 4) + 255) / 256;      // scale blocks
    int cb = 80;                             // W-conversion blocks (20480/256)

    cudaMemsetAsync(prep, 0, sizeof(int) * PRE_INTS);
    k_deg_conv     <<<eb + cb, 256>>>(src, dst, W1, W2, W3, e, eb);
    k_scan1        <<<nb, 1024>>>(n);
    k_scanfix      <<<(n + 255) / 256, 256>>>(n, e);
    k_scatter_scale<<<eb + sb, 256>>>(src, dst, feats, e, n, eb);

    k_layer128<<<740, 256>>>(h0, w1b, b1, h1, n, tiles);
    k_layer128<<<740, 256>>>(h1, w2b, b2, h0, n, tiles);
    k_pre3    <<<592, 256>>>(h0, hy, n, tiles);
    k_layer3  <<<(n * 32 + 255) / 256, 256>>>(hy, b3, Wp, bp, out, n);
}